// round 14
// baseline (speedup 1.0000x reference)
#include <cuda_runtime.h>
#include <cuda_bf16.h>
#include <cstdint>

#define Dh   1024
#define Bn   8
#define Tn   256
#define Vn   32000
#define Rn   2048   // Bn*Tn
#define RB   32     // rnn blocks

// ---------------- scratch (static device allocations; no cudaMalloc) ----------------
__device__ float          g_Wx[Rn * Dh];          // 8 MB
__device__ __nv_bfloat16  g_hbf[Rn * Dh];         // 4 MB  (h for final GEMM)
__device__ __nv_bfloat16  g_hcur[2][Bn * Dh];     // double-buffered current h (bf16)
__device__ __nv_bfloat16  g_xbf[Rn * Dh];         // 4 MB
__device__ __nv_bfloat16  g_Wbf[Dh * Dh];         // 2 MB
__device__ __nv_bfloat16  g_Ubf[Dh * Dh];         // 2 MB  (U in bf16 for mma)
__device__ __nv_bfloat16  g_Woutbf[Vn * Dh];      // 64 MB
__device__ float          g_rowsum[Rn];           // fused exp-sum per output row
__device__ volatile unsigned int g_slot[64 * 32]; // padded per-block epoch slots (128B apart)

// ---------------- cvt: W + U + Wout fp32->bf16, zero slots/rowsum ----------------
#define CVT_BLOCKS 2304
__global__ __launch_bounds__(256) void cvt_kernel(const float* __restrict__ W,
                                                  const float* __restrict__ U,
                                                  const float* __restrict__ Wout) {
    if (blockIdx.x == 0) {
        if (threadIdx.x < 64) g_slot[threadIdx.x * 32] = 0u;
        for (int i = threadIdx.x; i < Rn; i += 256) g_rowsum[i] = 0.0f;
    }
    const int nW    = Dh * Dh / 4;
    const int nU    = Dh * Dh / 4;
    const int nWout = Vn * Dh / 4;
    int i = blockIdx.x * 256 + threadIdx.x;
    const int stride = CVT_BLOCKS * 256;
    for (; i < nW + nU + nWout; i += stride) {
        float4 v;
        __nv_bfloat162* dst;
        if (i < nW) {
            v = ((const float4*)W)[i];
            dst = (__nv_bfloat162*)g_Wbf + 2 * (size_t)i;
        } else if (i < nW + nU) {
            int j = i - nW;
            v = ((const float4*)U)[j];
            dst = (__nv_bfloat162*)g_Ubf + 2 * (size_t)j;
        } else {
            int j = i - nW - nU;
            v = ((const float4*)Wout)[j];
            dst = (__nv_bfloat162*)g_Woutbf + 2 * (size_t)j;
        }
        dst[0] = __floats2bfloat162_rn(v.x, v.y);
        dst[1] = __floats2bfloat162_rn(v.z, v.w);
    }
}

// ---------------- embedding gather -> bf16 ----------------
__global__ __launch_bounds__(256) void embed_kernel(const int* __restrict__ idx,
                                                    const float* __restrict__ E) {
    int r = blockIdx.x;
    int id = idx[r];
    const float4* src = (const float4*)(E + (size_t)id * Dh);
    __nv_bfloat162* out = (__nv_bfloat162*)(g_xbf + (size_t)r * Dh);
    for (int i = threadIdx.x; i < Dh / 4; i += 256) {
        float4 v = src[i];
        out[2*i]   = __floats2bfloat162_rn(v.x, v.y);
        out[2*i+1] = __floats2bfloat162_rn(v.z, v.w);
    }
}

// ================= raw mma.sync bf16 NT GEMM: C[m,n] = sum_k A[m,k]*B[n,k] =================
#define BM 128
#define BN 128
#define BK 64
#define NST 3
#define AST (BM * BK * 2)
#define BST (BN * BK * 2)
#define GEMM_DSMEM (NST * (AST + BST))   // 96 KB

__device__ __forceinline__ uint32_t smem_u32(const void* p) {
    uint32_t a;
    asm("{ .reg .u64 t; cvta.to.shared.u64 t, %1; cvt.u32.u64 %0, t; }" : "=r"(a) : "l"(p));
    return a;
}
__device__ __forceinline__ void cp_async16(uint32_t dst, const void* src) {
    asm volatile("cp.async.cg.shared.global [%0], [%1], 16;" :: "r"(dst), "l"(src));
}
__device__ __forceinline__ void cp_commit() { asm volatile("cp.async.commit_group;"); }

__device__ __forceinline__ void ldsm4(uint32_t& r0, uint32_t& r1, uint32_t& r2, uint32_t& r3, uint32_t a) {
    asm volatile("ldmatrix.sync.aligned.m8n8.x4.shared.b16 {%0,%1,%2,%3}, [%4];"
                 : "=r"(r0), "=r"(r1), "=r"(r2), "=r"(r3) : "r"(a));
}
__device__ __forceinline__ void mma16816(float* d, const uint32_t* a, const uint32_t* b) {
    asm volatile("mma.sync.aligned.m16n8k16.row.col.f32.bf16.bf16.f32 "
                 "{%0,%1,%2,%3}, {%4,%5,%6,%7}, {%8,%9}, {%0,%1,%2,%3};"
                 : "+f"(d[0]), "+f"(d[1]), "+f"(d[2]), "+f"(d[3])
                 : "r"(a[0]), "r"(a[1]), "r"(a[2]), "r"(a[3]), "r"(b[0]), "r"(b[1]));
}

template <bool FUSE>
__global__ __launch_bounds__(256, 2) void gemm_mma(const __nv_bfloat16* __restrict__ A,
                                                   const __nv_bfloat16* __restrict__ Bm,
                                                   float* __restrict__ C,
                                                   int Nr, int Kr,
                                                   const float* __restrict__ bias,
                                                   float* __restrict__ rowsum) {
    extern __shared__ char smem[];
    const uint32_t sBase = smem_u32(smem);
    const uint32_t aS = sBase;
    const uint32_t bS = sBase + NST * AST;

    const int tid  = threadIdx.x;
    const int lane = tid & 31;
    const int wid  = tid >> 5;
    const int wm   = wid >> 2;
    const int wn   = wid & 3;
    const int bm = blockIdx.x, bn = blockIdx.y;
    const int KTILES = Kr / BK;

    uint32_t ld_phys[4];
    const __nv_bfloat16* aSrc[4];
    const __nv_bfloat16* bSrc[4];
    #pragma unroll
    for (int q = 0; q < 4; q++) {
        int task = q * 256 + tid;
        int row = task >> 3, ch = task & 7;
        uint32_t col = (uint32_t)ch * 16;
        ld_phys[q] = (uint32_t)row * 128 + (col ^ ((uint32_t)(row & 7) << 4));
        aSrc[q] = A  + (size_t)(bm * BM + row) * Kr + ch * 8;
        bSrc[q] = Bm + (size_t)(bn * BN + row) * Kr + ch * 8;
    }

    uint32_t aRowTerm[4], aPhase[4];
    const uint32_t aChunk = (uint32_t)(lane >> 4) * 16;
    #pragma unroll
    for (int i = 0; i < 4; i++) {
        int r = wm * 64 + i * 16 + (lane & 15);
        aRowTerm[i] = (uint32_t)r * 128;
        aPhase[i]   = (uint32_t)(r & 7) << 4;
    }
    uint32_t bRowTerm[2], bPhase[2];
    const uint32_t bChunk = (uint32_t)((lane >> 3) & 1) * 16;
    #pragma unroll
    for (int j = 0; j < 2; j++) {
        int n = wn * 32 + j * 16 + (lane & 7) + ((lane >> 4) << 3);
        bRowTerm[j] = (uint32_t)n * 128;
        bPhase[j]   = (uint32_t)(n & 7) << 4;
    }

    auto load_stage = [&](int st, int kt) {
        const int k0 = kt * BK;
        const uint32_t aOff = aS + st * AST;
        const uint32_t bOff = bS + st * BST;
        #pragma unroll
        for (int q = 0; q < 4; q++) {
            cp_async16(aOff + ld_phys[q], aSrc[q] + k0);
            cp_async16(bOff + ld_phys[q], bSrc[q] + k0);
        }
    };

    float acc[4][4][4];
    #pragma unroll
    for (int i = 0; i < 4; i++)
        #pragma unroll
        for (int j = 0; j < 4; j++)
            #pragma unroll
            for (int e = 0; e < 4; e++) acc[i][j][e] = 0.0f;

    load_stage(0, 0); cp_commit();
    load_stage(1, 1); cp_commit();

    for (int kt = 0; kt < KTILES; kt++) {
        const int st = kt % NST;
        asm volatile("cp.async.wait_group 1;" ::: "memory");
        __syncthreads();

        const int nf = kt + 2;
        if (nf < KTILES) load_stage(nf % NST, nf);
        cp_commit();

        const uint32_t aStage = aS + st * AST;
        const uint32_t bStage = bS + st * BST;
        #pragma unroll
        for (int s = 0; s < BK / 16; s++) {
            const uint32_t colA = (uint32_t)s * 32 + aChunk;
            const uint32_t colB = (uint32_t)s * 32 + bChunk;
            uint32_t a[4][4];
            #pragma unroll
            for (int i = 0; i < 4; i++)
                ldsm4(a[i][0], a[i][1], a[i][2], a[i][3],
                      aStage + aRowTerm[i] + (colA ^ aPhase[i]));
            uint32_t b[4][2];
            #pragma unroll
            for (int j = 0; j < 2; j++) {
                uint32_t r0, r1, r2, r3;
                ldsm4(r0, r1, r2, r3, bStage + bRowTerm[j] + (colB ^ bPhase[j]));
                b[2*j][0] = r0; b[2*j][1] = r1;
                b[2*j+1][0] = r2; b[2*j+1][1] = r3;
            }
            #pragma unroll
            for (int i = 0; i < 4; i++)
                #pragma unroll
                for (int j = 0; j < 4; j++)
                    mma16816(acc[i][j], a[i], b[j]);
        }
    }

    const int g = lane >> 2, tg = lane & 3;
    #pragma unroll
    for (int i = 0; i < 4; i++) {
        int row0 = bm * BM + wm * 64 + i * 16 + g;
        float p0 = 0.0f, p8 = 0.0f;
        #pragma unroll
        for (int j = 0; j < 4; j++) {
            int col = bn * BN + wn * 32 + j * 8 + tg * 2;
            float b0 = 0.0f, b1 = 0.0f;
            if (FUSE) { b0 = bias[col]; b1 = bias[col + 1]; }
            float v00 = acc[i][j][0] + b0, v01 = acc[i][j][1] + b1;
            float v10 = acc[i][j][2] + b0, v11 = acc[i][j][3] + b1;
            *(float2*)(C + (size_t)row0 * Nr + col)       = make_float2(v00, v01);
            *(float2*)(C + (size_t)(row0 + 8) * Nr + col) = make_float2(v10, v11);
            if (FUSE) {
                p0 += __expf(v00) + __expf(v01);
                p8 += __expf(v10) + __expf(v11);
            }
        }
        if (FUSE) {
            p0 += __shfl_xor_sync(0xffffffffu, p0, 1);
            p0 += __shfl_xor_sync(0xffffffffu, p0, 2);
            p8 += __shfl_xor_sync(0xffffffffu, p8, 1);
            p8 += __shfl_xor_sync(0xffffffffu, p8, 2);
            if (tg == 0) {
                atomicAdd(&rowsum[row0], p0);
                atomicAdd(&rowsum[row0 + 8], p8);
            }
        }
    }
}

// ====== persistent recurrence v9: 32 blocks x 512 threads, tensor-core, full-K ======
// Block bi owns 32 e's (E0 = bi*32). Warp w: eg = w>>2 (8-e group), kg = w&3 (k-range 256).
// U frags in registers; H broadcast via L2 (.cg). One smem round + shfl pack per step.
__global__ __launch_bounds__(512) void rnn_kernel(const float* __restrict__ bWv,
                                                  const float* __restrict__ bUv) {
    const int tid  = threadIdx.x;
    const int w    = tid >> 5;
    const int lane = tid & 31;
    const int bi   = blockIdx.x;
    const int E0   = bi * 32;
    const int eg   = w >> 2;           // 0..3  (8-e group within block)
    const int kg   = w & 3;            // 0..3  (k-range kg*256)
    const int bn   = lane >> 2;        // 0..7  (A row = batch, B col = e within group)
    const int bk   = (lane & 3) * 2;   // k pair base within k16

    // B frags: U[e = E0 + eg*8 + bn][k = kg*256 + s*16 + bk (+8)], s = 0..15
    const __nv_bfloat16* Ub = g_Ubf + (size_t)(E0 + eg * 8 + bn) * Dh + kg * 256 + bk;
    uint32_t bf[16][2];
    #pragma unroll
    for (int s = 0; s < 16; s++) {
        bf[s][0] = *(const uint32_t*)(Ub + s * 16);
        bf[s][1] = *(const uint32_t*)(Ub + s * 16 + 8);
    }

    int b = 0, el = 0;
    float bsum = 0.0f;
    if (tid < 256) {
        b = tid >> 5; el = tid & 31;
        bsum = bWv[E0 + el] + bUv[E0 + el];
    }

    __shared__ float sp[16][64];   // [warp][bn*8 + bk] partials

    for (int t = 0; t < Tn; t++) {
        float wx = 0.0f;
        if (tid < 256) wx = __ldcg(&g_Wx[(size_t)(b * Tn + t) * Dh + E0 + el]);

        float cE[4] = {0.f, 0.f, 0.f, 0.f};
        float cO[4] = {0.f, 0.f, 0.f, 0.f};
        if (t > 0) {
            const __nv_bfloat16* Hp = g_hcur[(t - 1) & 1] + (size_t)bn * Dh + kg * 256 + bk;
            #pragma unroll
            for (int s = 0; s < 16; s += 2) {
                uint32_t aaE[4], aaO[4];
                aaE[0] = __ldcg((const uint32_t*)(Hp + s * 16));
                aaE[1] = 0u;
                aaE[2] = __ldcg((const uint32_t*)(Hp + s * 16 + 8));
                aaE[3] = 0u;
                aaO[0] = __ldcg((const uint32_t*)(Hp + (s + 1) * 16));
                aaO[1] = 0u;
                aaO[2] = __ldcg((const uint32_t*)(Hp + (s + 1) * 16 + 8));
                aaO[3] = 0u;
                mma16816(cE, aaE, bf[s]);
                mma16816(cO, aaO, bf[s + 1]);
            }
        }
        *(float2*)&sp[w][bn * 8 + bk] = make_float2(cE[0] + cO[0], cE[1] + cO[1]);
        __syncthreads();

        if (tid < 256) {
            const int wb = (el >> 3) * 4;        // first warp (eg matching this e) at kg=0
            const int off = b * 8 + (el & 7);
            float s2 = wx + bsum
                     + sp[wb][off] + sp[wb + 1][off] + sp[wb + 2][off] + sp[wb + 3][off];
            float h = tanhf(s2);
            float hn = __shfl_down_sync(0xffffffffu, h, 1);
            if ((el & 1) == 0) {
                __nv_bfloat162 hv = __floats2bfloat162_rn(h, hn);
                *(__nv_bfloat162*)&g_hcur[t & 1][b * Dh + E0 + el] = hv;
                *(__nv_bfloat162*)&g_hbf[(size_t)(b * Tn + t) * Dh + E0 + el] = hv;
            }
        }
        __syncthreads();

        // ---- grid barrier: padded epoch slots, release store + 32-thread parallel poll ----
        if (tid == 0) {
            __threadfence();
            g_slot[bi * 32] = (unsigned)(t + 1);
        }
        for (;;) {
            bool ok = (tid < RB) ? (g_slot[tid * 32] >= (unsigned)(t + 1)) : true;
            if (__syncthreads_and(ok)) break;
        }
        __threadfence();
    }
}

// ---------------- final log_softmax subtract (single vectorized pass) ----------------
__global__ __launch_bounds__(256) void lse_final_kernel(float* __restrict__ C) {
    const int r = blockIdx.x;
    float4* row = (float4*)(C + (size_t)r * Vn);
    const float lse = __logf(g_rowsum[r]);
    for (int i = threadIdx.x; i < Vn / 4; i += 256) {
        float4 v = row[i];
        v.x -= lse; v.y -= lse; v.z -= lse; v.w -= lse;
        row[i] = v;
    }
}

// ---------------- launch ----------------
extern "C" void kernel_launch(void* const* d_in, const int* in_sizes, int n_in,
                              void* d_out, int out_size) {
    const int*   idx  = (const int*)d_in[0];
    const float* E    = (const float*)d_in[1];
    const float* W    = (const float*)d_in[2];
    const float* bW   = (const float*)d_in[3];
    const float* U    = (const float*)d_in[4];
    const float* bU   = (const float*)d_in[5];
    const float* Wout = (const float*)d_in[6];
    const float* bout = (const float*)d_in[7];
    float* out = (float*)d_out;

    void *p_xbf, *p_Wbf, *p_Woutbf, *p_Wx, *p_hbf, *p_rowsum;
    cudaGetSymbolAddress(&p_xbf,    g_xbf);
    cudaGetSymbolAddress(&p_Wbf,    g_Wbf);
    cudaGetSymbolAddress(&p_Woutbf, g_Woutbf);
    cudaGetSymbolAddress(&p_Wx,     g_Wx);
    cudaGetSymbolAddress(&p_hbf,    g_hbf);
    cudaGetSymbolAddress(&p_rowsum, g_rowsum);

    static int attr_set = 0;
    if (!attr_set) {
        cudaFuncSetAttribute(gemm_mma<false>, cudaFuncAttributeMaxDynamicSharedMemorySize, GEMM_DSMEM);
        cudaFuncSetAttribute(gemm_mma<true>,  cudaFuncAttributeMaxDynamicSharedMemorySize, GEMM_DSMEM);
        attr_set = 1;
    }

    // 1) cvt W/U/Wout + zero slots/rowsum
    cvt_kernel<<<CVT_BLOCKS, 256>>>(W, U, Wout);

    // 2) embedding gather
    embed_kernel<<<Rn, 256>>>(idx, E);

    // 3) input projection: Wx[r,e] = sum_d x[r,d] * W[e,d]
    gemm_mma<false><<<dim3(Rn / BM, Dh / BN), 256, GEMM_DSMEM>>>(
        (const __nv_bfloat16*)p_xbf, (const __nv_bfloat16*)p_Wbf, (float*)p_Wx,
        Dh, Dh, nullptr, nullptr);

    // 4) recurrence (tensor-core, 32 blocks x 512 threads)
    rnn_kernel<<<RB, 512>>>(bW, bU);

    // 5) output projection with fused bias + exp-sum epilogue
    gemm_mma<true><<<dim3(Rn / BM, Vn / BN), 256, GEMM_DSMEM>>>(
        (const __nv_bfloat16*)p_hbf, (const __nv_bfloat16*)p_Woutbf, out,
        Vn, Dh, bout, (float*)p_rowsum);

    // 6) final: subtract log(sum exp) per row
    lse_final_kernel<<<Rn, 256>>>(out);
}

// round 15
// speedup vs baseline: 1.3025x; 1.3025x over previous
#include <cuda_runtime.h>
#include <cuda_bf16.h>
#include <cstdint>

#define Dh   1024
#define Bn   8
#define Tn   256
#define Vn   32000
#define Rn   2048   // Bn*Tn

// ---------------- scratch (static device allocations; no cudaMalloc) ----------------
__device__ float          g_Wx[Rn * Dh];          // 8 MB
__device__ __nv_bfloat16  g_hbf[Rn * Dh];         // 4 MB  (h for final GEMM)
__device__ __nv_bfloat16  g_hcur[2][Bn * Dh];     // double-buffered current h (bf16)
__device__ __nv_bfloat16  g_xbf[Rn * Dh];         // 4 MB
__device__ __nv_bfloat16  g_Wbf[Dh * Dh];         // 2 MB
__device__ __nv_bfloat16  g_Ubf[Dh * Dh];         // 2 MB  (U in bf16 for mma)
__device__ __nv_bfloat16  g_Woutbf[Vn * Dh];      // 64 MB
__device__ float          g_rowsum[Rn];           // fused exp-sum per output row
__device__ volatile unsigned int g_slot[64 * 32]; // padded per-block epoch slots (128B apart)

// ---------------- cvt: W + U + Wout fp32->bf16, zero slots/rowsum ----------------
#define CVT_BLOCKS 2304
__global__ __launch_bounds__(256) void cvt_kernel(const float* __restrict__ W,
                                                  const float* __restrict__ U,
                                                  const float* __restrict__ Wout) {
    if (blockIdx.x == 0) {
        if (threadIdx.x < 64) g_slot[threadIdx.x * 32] = 0u;
        for (int i = threadIdx.x; i < Rn; i += 256) g_rowsum[i] = 0.0f;
    }
    const int nW    = Dh * Dh / 4;
    const int nU    = Dh * Dh / 4;
    const int nWout = Vn * Dh / 4;
    int i = blockIdx.x * 256 + threadIdx.x;
    const int stride = CVT_BLOCKS * 256;
    for (; i < nW + nU + nWout; i += stride) {
        float4 v;
        __nv_bfloat162* dst;
        if (i < nW) {
            v = ((const float4*)W)[i];
            dst = (__nv_bfloat162*)g_Wbf + 2 * (size_t)i;
        } else if (i < nW + nU) {
            int j = i - nW;
            v = ((const float4*)U)[j];
            dst = (__nv_bfloat162*)g_Ubf + 2 * (size_t)j;
        } else {
            int j = i - nW - nU;
            v = ((const float4*)Wout)[j];
            dst = (__nv_bfloat162*)g_Woutbf + 2 * (size_t)j;
        }
        dst[0] = __floats2bfloat162_rn(v.x, v.y);
        dst[1] = __floats2bfloat162_rn(v.z, v.w);
    }
}

// ---------------- embedding gather -> bf16 ----------------
__global__ __launch_bounds__(256) void embed_kernel(const int* __restrict__ idx,
                                                    const float* __restrict__ E) {
    int r = blockIdx.x;
    int id = idx[r];
    const float4* src = (const float4*)(E + (size_t)id * Dh);
    __nv_bfloat162* out = (__nv_bfloat162*)(g_xbf + (size_t)r * Dh);
    for (int i = threadIdx.x; i < Dh / 4; i += 256) {
        float4 v = src[i];
        out[2*i]   = __floats2bfloat162_rn(v.x, v.y);
        out[2*i+1] = __floats2bfloat162_rn(v.z, v.w);
    }
}

// ================= raw mma.sync bf16 NT GEMM: C[m,n] = sum_k A[m,k]*B[n,k] =================
#define BM 128
#define BN 128
#define BK 64
#define NST 3
#define AST (BM * BK * 2)
#define BST (BN * BK * 2)
#define GEMM_DSMEM (NST * (AST + BST))   // 96 KB

__device__ __forceinline__ uint32_t smem_u32(const void* p) {
    uint32_t a;
    asm("{ .reg .u64 t; cvta.to.shared.u64 t, %1; cvt.u32.u64 %0, t; }" : "=r"(a) : "l"(p));
    return a;
}
__device__ __forceinline__ void cp_async16(uint32_t dst, const void* src) {
    asm volatile("cp.async.cg.shared.global [%0], [%1], 16;" :: "r"(dst), "l"(src));
}
__device__ __forceinline__ void cp_commit() { asm volatile("cp.async.commit_group;"); }

__device__ __forceinline__ void ldsm4(uint32_t& r0, uint32_t& r1, uint32_t& r2, uint32_t& r3, uint32_t a) {
    asm volatile("ldmatrix.sync.aligned.m8n8.x4.shared.b16 {%0,%1,%2,%3}, [%4];"
                 : "=r"(r0), "=r"(r1), "=r"(r2), "=r"(r3) : "r"(a));
}
__device__ __forceinline__ void mma16816(float* d, const uint32_t* a, const uint32_t* b) {
    asm volatile("mma.sync.aligned.m16n8k16.row.col.f32.bf16.bf16.f32 "
                 "{%0,%1,%2,%3}, {%4,%5,%6,%7}, {%8,%9}, {%0,%1,%2,%3};"
                 : "+f"(d[0]), "+f"(d[1]), "+f"(d[2]), "+f"(d[3])
                 : "r"(a[0]), "r"(a[1]), "r"(a[2]), "r"(a[3]), "r"(b[0]), "r"(b[1]));
}

template <bool FUSE>
__global__ __launch_bounds__(256, 2) void gemm_mma(const __nv_bfloat16* __restrict__ A,
                                                   const __nv_bfloat16* __restrict__ Bm,
                                                   float* __restrict__ C,
                                                   int Nr, int Kr,
                                                   const float* __restrict__ bias,
                                                   float* __restrict__ rowsum) {
    extern __shared__ char smem[];
    const uint32_t sBase = smem_u32(smem);
    const uint32_t aS = sBase;
    const uint32_t bS = sBase + NST * AST;

    const int tid  = threadIdx.x;
    const int lane = tid & 31;
    const int wid  = tid >> 5;
    const int wm   = wid >> 2;
    const int wn   = wid & 3;
    const int bm = blockIdx.x, bn = blockIdx.y;
    const int KTILES = Kr / BK;

    uint32_t ld_phys[4];
    const __nv_bfloat16* aSrc[4];
    const __nv_bfloat16* bSrc[4];
    #pragma unroll
    for (int q = 0; q < 4; q++) {
        int task = q * 256 + tid;
        int row = task >> 3, ch = task & 7;
        uint32_t col = (uint32_t)ch * 16;
        ld_phys[q] = (uint32_t)row * 128 + (col ^ ((uint32_t)(row & 7) << 4));
        aSrc[q] = A  + (size_t)(bm * BM + row) * Kr + ch * 8;
        bSrc[q] = Bm + (size_t)(bn * BN + row) * Kr + ch * 8;
    }

    uint32_t aRowTerm[4], aPhase[4];
    const uint32_t aChunk = (uint32_t)(lane >> 4) * 16;
    #pragma unroll
    for (int i = 0; i < 4; i++) {
        int r = wm * 64 + i * 16 + (lane & 15);
        aRowTerm[i] = (uint32_t)r * 128;
        aPhase[i]   = (uint32_t)(r & 7) << 4;
    }
    uint32_t bRowTerm[2], bPhase[2];
    const uint32_t bChunk = (uint32_t)((lane >> 3) & 1) * 16;
    #pragma unroll
    for (int j = 0; j < 2; j++) {
        int n = wn * 32 + j * 16 + (lane & 7) + ((lane >> 4) << 3);
        bRowTerm[j] = (uint32_t)n * 128;
        bPhase[j]   = (uint32_t)(n & 7) << 4;
    }

    auto load_stage = [&](int st, int kt) {
        const int k0 = kt * BK;
        const uint32_t aOff = aS + st * AST;
        const uint32_t bOff = bS + st * BST;
        #pragma unroll
        for (int q = 0; q < 4; q++) {
            cp_async16(aOff + ld_phys[q], aSrc[q] + k0);
            cp_async16(bOff + ld_phys[q], bSrc[q] + k0);
        }
    };

    float acc[4][4][4];
    #pragma unroll
    for (int i = 0; i < 4; i++)
        #pragma unroll
        for (int j = 0; j < 4; j++)
            #pragma unroll
            for (int e = 0; e < 4; e++) acc[i][j][e] = 0.0f;

    load_stage(0, 0); cp_commit();
    load_stage(1, 1); cp_commit();

    for (int kt = 0; kt < KTILES; kt++) {
        const int st = kt % NST;
        asm volatile("cp.async.wait_group 1;" ::: "memory");
        __syncthreads();

        const int nf = kt + 2;
        if (nf < KTILES) load_stage(nf % NST, nf);
        cp_commit();

        const uint32_t aStage = aS + st * AST;
        const uint32_t bStage = bS + st * BST;
        #pragma unroll
        for (int s = 0; s < BK / 16; s++) {
            const uint32_t colA = (uint32_t)s * 32 + aChunk;
            const uint32_t colB = (uint32_t)s * 32 + bChunk;
            uint32_t a[4][4];
            #pragma unroll
            for (int i = 0; i < 4; i++)
                ldsm4(a[i][0], a[i][1], a[i][2], a[i][3],
                      aStage + aRowTerm[i] + (colA ^ aPhase[i]));
            uint32_t b[4][2];
            #pragma unroll
            for (int j = 0; j < 2; j++) {
                uint32_t r0, r1, r2, r3;
                ldsm4(r0, r1, r2, r3, bStage + bRowTerm[j] + (colB ^ bPhase[j]));
                b[2*j][0] = r0; b[2*j][1] = r1;
                b[2*j+1][0] = r2; b[2*j+1][1] = r3;
            }
            #pragma unroll
            for (int i = 0; i < 4; i++)
                #pragma unroll
                for (int j = 0; j < 4; j++)
                    mma16816(acc[i][j], a[i], b[j]);
        }
    }

    const int g = lane >> 2, tg = lane & 3;
    #pragma unroll
    for (int i = 0; i < 4; i++) {
        int row0 = bm * BM + wm * 64 + i * 16 + g;
        float p0 = 0.0f, p8 = 0.0f;
        #pragma unroll
        for (int j = 0; j < 4; j++) {
            int col = bn * BN + wn * 32 + j * 8 + tg * 2;
            float b0 = 0.0f, b1 = 0.0f;
            if (FUSE) { b0 = bias[col]; b1 = bias[col + 1]; }
            float v00 = acc[i][j][0] + b0, v01 = acc[i][j][1] + b1;
            float v10 = acc[i][j][2] + b0, v11 = acc[i][j][3] + b1;
            *(float2*)(C + (size_t)row0 * Nr + col)       = make_float2(v00, v01);
            *(float2*)(C + (size_t)(row0 + 8) * Nr + col) = make_float2(v10, v11);
            if (FUSE) {
                p0 += __expf(v00) + __expf(v01);
                p8 += __expf(v10) + __expf(v11);
            }
        }
        if (FUSE) {
            p0 += __shfl_xor_sync(0xffffffffu, p0, 1);
            p0 += __shfl_xor_sync(0xffffffffu, p0, 2);
            p8 += __shfl_xor_sync(0xffffffffu, p8, 1);
            p8 += __shfl_xor_sync(0xffffffffu, p8, 2);
            if (tg == 0) {
                atomicAdd(&rowsum[row0], p0);
                atomicAdd(&rowsum[row0 + 8], p8);
            }
        }
    }
}

// ====== persistent recurrence v8b: 64 blocks x 256 threads, tensor-core, merged phases ======
// Block bi owns 16 e's (E0 = bi*16). Warp w owns k-range [w*128, w*128+128).
// U slice as bf16 mma B-fragments in registers. H_t broadcast via L2 (bf16).
__global__ __launch_bounds__(256) void rnn_kernel(const float* __restrict__ bWv,
                                                  const float* __restrict__ bUv) {
    const int tid  = threadIdx.x;
    const int w    = tid >> 5;
    const int lane = tid & 31;
    const int bi   = blockIdx.x;
    const int E0   = bi * 16;

    const int bn = lane >> 2;          // mma row/col group: batch row (A) / n (B)
    const int bk = (lane & 3) * 2;     // k pair within k16

    // B fragments: U[n = E0 + j*8 + bn][k = w*128 + s*16 + bk (+8)]
    uint32_t bf[2][8][2];
    #pragma unroll
    for (int j = 0; j < 2; j++)
        #pragma unroll
        for (int s = 0; s < 8; s++) {
            const __nv_bfloat16* up = g_Ubf + (size_t)(E0 + j * 8 + bn) * Dh + w * 128 + s * 16 + bk;
            bf[j][s][0] = *(const uint32_t*)up;
            bf[j][s][1] = *(const uint32_t*)(up + 8);
        }

    int bb = 0, el = 0;
    float bsum = 0.0f;
    if (tid < 128) {
        bb = tid >> 4; el = tid & 15;
        bsum = bWv[E0 + el] + bUv[E0 + el];
    }

    __shared__ float sp[8 * 128];   // per-warp partials [w][b*16+e_local]

    const uint32_t zero = 0u;

    for (int t = 0; t < Tn; t++) {
        float wx = 0.0f;
        if (tid < 128) wx = __ldcg(&g_Wx[(size_t)(bb * Tn + t) * Dh + E0 + el]);

        float c[2][4];
        #pragma unroll
        for (int j = 0; j < 2; j++)
            #pragma unroll
            for (int q = 0; q < 4; q++) c[j][q] = 0.0f;

        if (t > 0) {
            const __nv_bfloat16* Hp = g_hcur[(t - 1) & 1];
            #pragma unroll
            for (int s = 0; s < 8; s++) {
                const __nv_bfloat16* hp = Hp + (size_t)bn * Dh + w * 128 + s * 16 + bk;
                uint32_t aa[4];
                aa[0] = __ldcg((const uint32_t*)hp);
                aa[1] = zero;
                aa[2] = __ldcg((const uint32_t*)(hp + 8));
                aa[3] = zero;
                mma16816(c[0], aa, bf[0][s]);
                mma16816(c[1], aa, bf[1][s]);
            }
        }

        // write warp partials: c[j][0,1] = (b=bn, e_local = j*8 + bk, +1)
        #pragma unroll
        for (int j = 0; j < 2; j++)
            *(float2*)&sp[w * 128 + bn * 16 + j * 8 + bk] = make_float2(c[j][0], c[j][1]);
        __syncthreads();

        // reduce + tanh + DIRECT bf16 store of own h (no pack phase)
        __nv_bfloat16 hb;
        if (tid < 128) {
            float s2 = wx + bsum;
            #pragma unroll
            for (int w8 = 0; w8 < 8; w8++) s2 += sp[w8 * 128 + tid];
            hb = __float2bfloat16(tanhf(s2));
            g_hcur[t & 1][bb * Dh + E0 + el] = hb;
        }
        __syncthreads();

        // arrival FIRST (critical for other blocks), history store behind it
        if (tid == 0) {
            __threadfence();
            g_slot[bi * 32] = (unsigned)(t + 1);
        }
        if (tid < 128)
            g_hbf[(size_t)(bb * Tn + t) * Dh + E0 + el] = hb;

        // poll: 64-thread parallel
        for (;;) {
            bool ok = (tid < 64) ? (g_slot[tid * 32] >= (unsigned)(t + 1)) : true;
            if (__syncthreads_and(ok)) break;
        }
        __threadfence();
    }
}

// ---------------- final log_softmax subtract (single vectorized pass) ----------------
__global__ __launch_bounds__(256) void lse_final_kernel(float* __restrict__ C) {
    const int r = blockIdx.x;
    float4* row = (float4*)(C + (size_t)r * Vn);
    const float lse = __logf(g_rowsum[r]);
    for (int i = threadIdx.x; i < Vn / 4; i += 256) {
        float4 v = row[i];
        v.x -= lse; v.y -= lse; v.z -= lse; v.w -= lse;
        row[i] = v;
    }
}

// ---------------- launch ----------------
extern "C" void kernel_launch(void* const* d_in, const int* in_sizes, int n_in,
                              void* d_out, int out_size) {
    const int*   idx  = (const int*)d_in[0];
    const float* E    = (const float*)d_in[1];
    const float* W    = (const float*)d_in[2];
    const float* bW   = (const float*)d_in[3];
    const float* U    = (const float*)d_in[4];
    const float* bU   = (const float*)d_in[5];
    const float* Wout = (const float*)d_in[6];
    const float* bout = (const float*)d_in[7];
    float* out = (float*)d_out;

    void *p_xbf, *p_Wbf, *p_Woutbf, *p_Wx, *p_hbf, *p_rowsum;
    cudaGetSymbolAddress(&p_xbf,    g_xbf);
    cudaGetSymbolAddress(&p_Wbf,    g_Wbf);
    cudaGetSymbolAddress(&p_Woutbf, g_Woutbf);
    cudaGetSymbolAddress(&p_Wx,     g_Wx);
    cudaGetSymbolAddress(&p_hbf,    g_hbf);
    cudaGetSymbolAddress(&p_rowsum, g_rowsum);

    static int attr_set = 0;
    if (!attr_set) {
        cudaFuncSetAttribute(gemm_mma<false>, cudaFuncAttributeMaxDynamicSharedMemorySize, GEMM_DSMEM);
        cudaFuncSetAttribute(gemm_mma<true>,  cudaFuncAttributeMaxDynamicSharedMemorySize, GEMM_DSMEM);
        attr_set = 1;
    }

    // 1) cvt W/U/Wout + zero slots/rowsum
    cvt_kernel<<<CVT_BLOCKS, 256>>>(W, U, Wout);

    // 2) embedding gather
    embed_kernel<<<Rn, 256>>>(idx, E);

    // 3) input projection: Wx[r,e] = sum_d x[r,d] * W[e,d]
    gemm_mma<false><<<dim3(Rn / BM, Dh / BN), 256, GEMM_DSMEM>>>(
        (const __nv_bfloat16*)p_xbf, (const __nv_bfloat16*)p_Wbf, (float*)p_Wx,
        Dh, Dh, nullptr, nullptr);

    // 4) recurrence (tensor-core, 64 blocks x 256 threads)
    rnn_kernel<<<64, 256>>>(bW, bU);

    // 5) output projection with fused bias + exp-sum epilogue
    gemm_mma<true><<<dim3(Rn / BM, Vn / BN), 256, GEMM_DSMEM>>>(
        (const __nv_bfloat16*)p_hbf, (const __nv_bfloat16*)p_Woutbf, out,
        Vn, Dh, bout, (float*)p_rowsum);

    // 6) final: subtract log(sum exp) per row
    lse_final_kernel<<<Rn, 256>>>(out);
}

// round 16
// speedup vs baseline: 1.4728x; 1.1307x over previous
#include <cuda_runtime.h>
#include <cuda_bf16.h>
#include <cstdint>

#define Dh   1024
#define Bn   8
#define Tn   256
#define Vn   32000
#define Rn   2048   // Bn*Tn
#define RB   32     // rnn blocks

// ---------------- scratch (static device allocations; no cudaMalloc) ----------------
__device__ float          g_Wx[Rn * Dh];          // 8 MB
__device__ __nv_bfloat16  g_hbf[Rn * Dh];         // 4 MB  (h for final GEMM)
__device__ __nv_bfloat16  g_hcur[2][Bn * Dh];     // double-buffered current h (bf16)
__device__ __nv_bfloat16  g_xbf[Rn * Dh];         // 4 MB
__device__ __nv_bfloat16  g_Wbf[Dh * Dh];         // 2 MB
__device__ __nv_bfloat16  g_Ubf[Dh * Dh];         // 2 MB  (U in bf16 for mma)
__device__ __nv_bfloat16  g_Woutbf[Vn * Dh];      // 64 MB
__device__ float          g_rowsum[Rn];           // fused exp-sum per output row
__device__ volatile unsigned int g_slot[64 * 32]; // padded per-block epoch slots (128B apart)

// ---------------- cvt: W + U + Wout fp32->bf16, zero slots/rowsum ----------------
#define CVT_BLOCKS 2304
__global__ __launch_bounds__(256) void cvt_kernel(const float* __restrict__ W,
                                                  const float* __restrict__ U,
                                                  const float* __restrict__ Wout) {
    if (blockIdx.x == 0) {
        if (threadIdx.x < 64) g_slot[threadIdx.x * 32] = 0u;
        for (int i = threadIdx.x; i < Rn; i += 256) g_rowsum[i] = 0.0f;
    }
    const int nW    = Dh * Dh / 4;
    const int nU    = Dh * Dh / 4;
    const int nWout = Vn * Dh / 4;
    int i = blockIdx.x * 256 + threadIdx.x;
    const int stride = CVT_BLOCKS * 256;
    for (; i < nW + nU + nWout; i += stride) {
        float4 v;
        __nv_bfloat162* dst;
        if (i < nW) {
            v = ((const float4*)W)[i];
            dst = (__nv_bfloat162*)g_Wbf + 2 * (size_t)i;
        } else if (i < nW + nU) {
            int j = i - nW;
            v = ((const float4*)U)[j];
            dst = (__nv_bfloat162*)g_Ubf + 2 * (size_t)j;
        } else {
            int j = i - nW - nU;
            v = ((const float4*)Wout)[j];
            dst = (__nv_bfloat162*)g_Woutbf + 2 * (size_t)j;
        }
        dst[0] = __floats2bfloat162_rn(v.x, v.y);
        dst[1] = __floats2bfloat162_rn(v.z, v.w);
    }
}

// ---------------- embedding gather -> bf16 ----------------
__global__ __launch_bounds__(256) void embed_kernel(const int* __restrict__ idx,
                                                    const float* __restrict__ E) {
    int r = blockIdx.x;
    int id = idx[r];
    const float4* src = (const float4*)(E + (size_t)id * Dh);
    __nv_bfloat162* out = (__nv_bfloat162*)(g_xbf + (size_t)r * Dh);
    for (int i = threadIdx.x; i < Dh / 4; i += 256) {
        float4 v = src[i];
        out[2*i]   = __floats2bfloat162_rn(v.x, v.y);
        out[2*i+1] = __floats2bfloat162_rn(v.z, v.w);
    }
}

// ================= raw mma.sync bf16 NT GEMM: C[m,n] = sum_k A[m,k]*B[n,k] =================
#define BM 128
#define BN 128
#define BK 64
#define NST 3
#define AST (BM * BK * 2)
#define BST (BN * BK * 2)
#define GEMM_DSMEM (NST * (AST + BST))   // 96 KB

__device__ __forceinline__ uint32_t smem_u32(const void* p) {
    uint32_t a;
    asm("{ .reg .u64 t; cvta.to.shared.u64 t, %1; cvt.u32.u64 %0, t; }" : "=r"(a) : "l"(p));
    return a;
}
__device__ __forceinline__ void cp_async16(uint32_t dst, const void* src) {
    asm volatile("cp.async.cg.shared.global [%0], [%1], 16;" :: "r"(dst), "l"(src));
}
__device__ __forceinline__ void cp_commit() { asm volatile("cp.async.commit_group;"); }

__device__ __forceinline__ void ldsm4(uint32_t& r0, uint32_t& r1, uint32_t& r2, uint32_t& r3, uint32_t a) {
    asm volatile("ldmatrix.sync.aligned.m8n8.x4.shared.b16 {%0,%1,%2,%3}, [%4];"
                 : "=r"(r0), "=r"(r1), "=r"(r2), "=r"(r3) : "r"(a));
}
__device__ __forceinline__ void mma16816(float* d, const uint32_t* a, const uint32_t* b) {
    asm volatile("mma.sync.aligned.m16n8k16.row.col.f32.bf16.bf16.f32 "
                 "{%0,%1,%2,%3}, {%4,%5,%6,%7}, {%8,%9}, {%0,%1,%2,%3};"
                 : "+f"(d[0]), "+f"(d[1]), "+f"(d[2]), "+f"(d[3])
                 : "r"(a[0]), "r"(a[1]), "r"(a[2]), "r"(a[3]), "r"(b[0]), "r"(b[1]));
}

template <bool FUSE>
__global__ __launch_bounds__(256, 2) void gemm_mma(const __nv_bfloat16* __restrict__ A,
                                                   const __nv_bfloat16* __restrict__ Bm,
                                                   float* __restrict__ C,
                                                   int Nr, int Kr,
                                                   const float* __restrict__ bias,
                                                   float* __restrict__ rowsum) {
    extern __shared__ char smem[];
    const uint32_t sBase = smem_u32(smem);
    const uint32_t aS = sBase;
    const uint32_t bS = sBase + NST * AST;

    const int tid  = threadIdx.x;
    const int lane = tid & 31;
    const int wid  = tid >> 5;
    const int wm   = wid >> 2;
    const int wn   = wid & 3;
    const int bm = blockIdx.x, bn = blockIdx.y;
    const int KTILES = Kr / BK;

    uint32_t ld_phys[4];
    const __nv_bfloat16* aSrc[4];
    const __nv_bfloat16* bSrc[4];
    #pragma unroll
    for (int q = 0; q < 4; q++) {
        int task = q * 256 + tid;
        int row = task >> 3, ch = task & 7;
        uint32_t col = (uint32_t)ch * 16;
        ld_phys[q] = (uint32_t)row * 128 + (col ^ ((uint32_t)(row & 7) << 4));
        aSrc[q] = A  + (size_t)(bm * BM + row) * Kr + ch * 8;
        bSrc[q] = Bm + (size_t)(bn * BN + row) * Kr + ch * 8;
    }

    uint32_t aRowTerm[4], aPhase[4];
    const uint32_t aChunk = (uint32_t)(lane >> 4) * 16;
    #pragma unroll
    for (int i = 0; i < 4; i++) {
        int r = wm * 64 + i * 16 + (lane & 15);
        aRowTerm[i] = (uint32_t)r * 128;
        aPhase[i]   = (uint32_t)(r & 7) << 4;
    }
    uint32_t bRowTerm[2], bPhase[2];
    const uint32_t bChunk = (uint32_t)((lane >> 3) & 1) * 16;
    #pragma unroll
    for (int j = 0; j < 2; j++) {
        int n = wn * 32 + j * 16 + (lane & 7) + ((lane >> 4) << 3);
        bRowTerm[j] = (uint32_t)n * 128;
        bPhase[j]   = (uint32_t)(n & 7) << 4;
    }

    auto load_stage = [&](int st, int kt) {
        const int k0 = kt * BK;
        const uint32_t aOff = aS + st * AST;
        const uint32_t bOff = bS + st * BST;
        #pragma unroll
        for (int q = 0; q < 4; q++) {
            cp_async16(aOff + ld_phys[q], aSrc[q] + k0);
            cp_async16(bOff + ld_phys[q], bSrc[q] + k0);
        }
    };

    float acc[4][4][4];
    #pragma unroll
    for (int i = 0; i < 4; i++)
        #pragma unroll
        for (int j = 0; j < 4; j++)
            #pragma unroll
            for (int e = 0; e < 4; e++) acc[i][j][e] = 0.0f;

    load_stage(0, 0); cp_commit();
    load_stage(1, 1); cp_commit();

    for (int kt = 0; kt < KTILES; kt++) {
        const int st = kt % NST;
        asm volatile("cp.async.wait_group 1;" ::: "memory");
        __syncthreads();

        const int nf = kt + 2;
        if (nf < KTILES) load_stage(nf % NST, nf);
        cp_commit();

        const uint32_t aStage = aS + st * AST;
        const uint32_t bStage = bS + st * BST;
        #pragma unroll
        for (int s = 0; s < BK / 16; s++) {
            const uint32_t colA = (uint32_t)s * 32 + aChunk;
            const uint32_t colB = (uint32_t)s * 32 + bChunk;
            uint32_t a[4][4];
            #pragma unroll
            for (int i = 0; i < 4; i++)
                ldsm4(a[i][0], a[i][1], a[i][2], a[i][3],
                      aStage + aRowTerm[i] + (colA ^ aPhase[i]));
            uint32_t b[4][2];
            #pragma unroll
            for (int j = 0; j < 2; j++) {
                uint32_t r0, r1, r2, r3;
                ldsm4(r0, r1, r2, r3, bStage + bRowTerm[j] + (colB ^ bPhase[j]));
                b[2*j][0] = r0; b[2*j][1] = r1;
                b[2*j+1][0] = r2; b[2*j+1][1] = r3;
            }
            #pragma unroll
            for (int i = 0; i < 4; i++)
                #pragma unroll
                for (int j = 0; j < 4; j++)
                    mma16816(acc[i][j], a[i], b[j]);
        }
    }

    const int g = lane >> 2, tg = lane & 3;
    #pragma unroll
    for (int i = 0; i < 4; i++) {
        int row0 = bm * BM + wm * 64 + i * 16 + g;
        float p0 = 0.0f, p8 = 0.0f;
        #pragma unroll
        for (int j = 0; j < 4; j++) {
            int col = bn * BN + wn * 32 + j * 8 + tg * 2;
            float b0 = 0.0f, b1 = 0.0f;
            if (FUSE) { b0 = bias[col]; b1 = bias[col + 1]; }
            float v00 = acc[i][j][0] + b0, v01 = acc[i][j][1] + b1;
            float v10 = acc[i][j][2] + b0, v11 = acc[i][j][3] + b1;
            *(float2*)(C + (size_t)row0 * Nr + col)       = make_float2(v00, v01);
            *(float2*)(C + (size_t)(row0 + 8) * Nr + col) = make_float2(v10, v11);
            if (FUSE) {
                p0 += __expf(v00) + __expf(v01);
                p8 += __expf(v10) + __expf(v11);
            }
        }
        if (FUSE) {
            p0 += __shfl_xor_sync(0xffffffffu, p0, 1);
            p0 += __shfl_xor_sync(0xffffffffu, p0, 2);
            p8 += __shfl_xor_sync(0xffffffffu, p8, 1);
            p8 += __shfl_xor_sync(0xffffffffu, p8, 2);
            if (tg == 0) {
                atomicAdd(&rowsum[row0], p0);
                atomicAdd(&rowsum[row0 + 8], p8);
            }
        }
    }
}

// ====== persistent recurrence v10: R13's v8 structure, 32 blocks x 256 threads ======
// Block bi owns 32 e's (E0 = bi*32). Warp w owns k-range [w*128, w*128+128).
// U slice as bf16 mma B-fragments in registers (4 N-tiles). H broadcast via L2 (bf16).
__global__ __launch_bounds__(256) void rnn_kernel(const float* __restrict__ bWv,
                                                  const float* __restrict__ bUv) {
    const int tid  = threadIdx.x;
    const int w    = tid >> 5;
    const int lane = tid & 31;
    const int bi   = blockIdx.x;
    const int E0   = bi * 32;

    const int bn = lane >> 2;          // mma row/col group: batch row (A) / n (B)
    const int bk = (lane & 3) * 2;     // k pair within k16

    // B fragments: U[n = E0 + j*8 + bn][k = w*128 + s*16 + bk (+8)], j = 0..3
    uint32_t bf[4][8][2];
    #pragma unroll
    for (int j = 0; j < 4; j++)
        #pragma unroll
        for (int s = 0; s < 8; s++) {
            const __nv_bfloat16* up = g_Ubf + (size_t)(E0 + j * 8 + bn) * Dh + w * 128 + s * 16 + bk;
            bf[j][s][0] = *(const uint32_t*)up;
            bf[j][s][1] = *(const uint32_t*)(up + 8);
        }

    const int bb = tid >> 5;           // batch for reduce phase (0..7)
    const int el = tid & 31;           // e_local for reduce phase (0..31)
    const float bsum = bWv[E0 + el] + bUv[E0 + el];

    __shared__ float sp[8 * 256];   // per-warp partials [w][b*32 + e_local]
    __shared__ float sh2[256];      // h floats [b*32 + e_local]  (b in tid>>5 order)

    const uint32_t zero = 0u;

    for (int t = 0; t < Tn; t++) {
        float wx = __ldcg(&g_Wx[(size_t)(bb * Tn + t) * Dh + E0 + el]);

        float c[4][4];
        #pragma unroll
        for (int j = 0; j < 4; j++)
            #pragma unroll
            for (int q = 0; q < 4; q++) c[j][q] = 0.0f;

        if (t > 0) {
            const __nv_bfloat16* Hp = g_hcur[(t - 1) & 1];
            #pragma unroll
            for (int s = 0; s < 8; s++) {
                const __nv_bfloat16* hp = Hp + (size_t)bn * Dh + w * 128 + s * 16 + bk;
                uint32_t aa[4];
                aa[0] = __ldcg((const uint32_t*)hp);
                aa[1] = zero;
                aa[2] = __ldcg((const uint32_t*)(hp + 8));
                aa[3] = zero;
                mma16816(c[0], aa, bf[0][s]);
                mma16816(c[1], aa, bf[1][s]);
                mma16816(c[2], aa, bf[2][s]);
                mma16816(c[3], aa, bf[3][s]);
            }
        }

        // write warp partials: c[j][0,1] = (b=bn, e_local = j*8 + bk, +1)
        #pragma unroll
        for (int j = 0; j < 4; j++)
            *(float2*)&sp[w * 256 + bn * 32 + j * 8 + bk] = make_float2(c[j][0], c[j][1]);
        __syncthreads();

        {
            float s2 = wx + bsum;
            #pragma unroll
            for (int w8 = 0; w8 < 8; w8++) s2 += sp[w8 * 256 + tid];
            sh2[tid] = tanhf(s2);
        }
        __syncthreads();

        if (tid < 128) {
            int b2 = tid >> 4, e2 = (tid & 15) * 2;
            __nv_bfloat162 hv = __floats2bfloat162_rn(sh2[b2 * 32 + e2], sh2[b2 * 32 + e2 + 1]);
            *(__nv_bfloat162*)&g_hcur[t & 1][b2 * Dh + E0 + e2] = hv;
            *(__nv_bfloat162*)&g_hbf[(size_t)(b2 * Tn + t) * Dh + E0 + e2] = hv;
        }
        __syncthreads();

        // ---- grid barrier: padded epoch slots, release store + 32-thread parallel poll ----
        if (tid == 0) {
            __threadfence();
            g_slot[bi * 32] = (unsigned)(t + 1);
        }
        for (;;) {
            bool ok = (tid < RB) ? (g_slot[tid * 32] >= (unsigned)(t + 1)) : true;
            if (__syncthreads_and(ok)) break;
        }
        __threadfence();
    }
}

// ---------------- final log_softmax subtract (single vectorized pass) ----------------
__global__ __launch_bounds__(256) void lse_final_kernel(float* __restrict__ C) {
    const int r = blockIdx.x;
    float4* row = (float4*)(C + (size_t)r * Vn);
    const float lse = __logf(g_rowsum[r]);
    for (int i = threadIdx.x; i < Vn / 4; i += 256) {
        float4 v = row[i];
        v.x -= lse; v.y -= lse; v.z -= lse; v.w -= lse;
        row[i] = v;
    }
}

// ---------------- launch ----------------
extern "C" void kernel_launch(void* const* d_in, const int* in_sizes, int n_in,
                              void* d_out, int out_size) {
    const int*   idx  = (const int*)d_in[0];
    const float* E    = (const float*)d_in[1];
    const float* W    = (const float*)d_in[2];
    const float* bW   = (const float*)d_in[3];
    const float* U    = (const float*)d_in[4];
    const float* bU   = (const float*)d_in[5];
    const float* Wout = (const float*)d_in[6];
    const float* bout = (const float*)d_in[7];
    float* out = (float*)d_out;

    void *p_xbf, *p_Wbf, *p_Woutbf, *p_Wx, *p_hbf, *p_rowsum;
    cudaGetSymbolAddress(&p_xbf,    g_xbf);
    cudaGetSymbolAddress(&p_Wbf,    g_Wbf);
    cudaGetSymbolAddress(&p_Woutbf, g_Woutbf);
    cudaGetSymbolAddress(&p_Wx,     g_Wx);
    cudaGetSymbolAddress(&p_hbf,    g_hbf);
    cudaGetSymbolAddress(&p_rowsum, g_rowsum);

    static int attr_set = 0;
    if (!attr_set) {
        cudaFuncSetAttribute(gemm_mma<false>, cudaFuncAttributeMaxDynamicSharedMemorySize, GEMM_DSMEM);
        cudaFuncSetAttribute(gemm_mma<true>,  cudaFuncAttributeMaxDynamicSharedMemorySize, GEMM_DSMEM);
        attr_set = 1;
    }

    // 1) cvt W/U/Wout + zero slots/rowsum
    cvt_kernel<<<CVT_BLOCKS, 256>>>(W, U, Wout);

    // 2) embedding gather
    embed_kernel<<<Rn, 256>>>(idx, E);

    // 3) input projection: Wx[r,e] = sum_d x[r,d] * W[e,d]
    gemm_mma<false><<<dim3(Rn / BM, Dh / BN), 256, GEMM_DSMEM>>>(
        (const __nv_bfloat16*)p_xbf, (const __nv_bfloat16*)p_Wbf, (float*)p_Wx,
        Dh, Dh, nullptr, nullptr);

    // 4) recurrence (tensor-core, 32 blocks x 256 threads)
    rnn_kernel<<<RB, 256>>>(bW, bU);

    // 5) output projection with fused bias + exp-sum epilogue
    gemm_mma<true><<<dim3(Rn / BM, Vn / BN), 256, GEMM_DSMEM>>>(
        (const __nv_bfloat16*)p_hbf, (const __nv_bfloat16*)p_Woutbf, out,
        Vn, Dh, bout, (float*)p_rowsum);

    // 6) final: subtract log(sum exp) per row
    lse_final_kernel<<<Rn, 256>>>(out);
}

// round 17
// speedup vs baseline: 1.4730x; 1.0002x over previous
#include <cuda_runtime.h>
#include <cuda_bf16.h>
#include <cstdint>

#define Dh   1024
#define Bn   8
#define Tn   256
#define Vn   32000
#define Rn   2048   // Bn*Tn
#define RB   32     // rnn blocks (2 groups x 16)

// ---------------- scratch (static device allocations; no cudaMalloc) ----------------
__device__ float          g_Wx[Rn * Dh];          // 8 MB
__device__ __nv_bfloat16  g_hbf[Rn * Dh];         // 4 MB  (h for final GEMM)
__device__ __nv_bfloat16  g_hcur[2][Bn * Dh];     // double-buffered current h (bf16)
__device__ __nv_bfloat16  g_xbf[Rn * Dh];         // 4 MB
__device__ __nv_bfloat16  g_Wbf[Dh * Dh];         // 2 MB
__device__ __nv_bfloat16  g_Ubf[Dh * Dh];         // 2 MB  (U in bf16 for mma)
__device__ __nv_bfloat16  g_Woutbf[Vn * Dh];      // 64 MB
__device__ float          g_rowsum[Rn];           // fused exp-sum per output row
__device__ volatile unsigned int g_slot[64 * 32]; // padded per-block epoch slots (128B apart)

// ---------------- cvt: W + U + Wout fp32->bf16, zero slots/rowsum ----------------
#define CVT_BLOCKS 2304
__global__ __launch_bounds__(256) void cvt_kernel(const float* __restrict__ W,
                                                  const float* __restrict__ U,
                                                  const float* __restrict__ Wout) {
    if (blockIdx.x == 0) {
        if (threadIdx.x < 64) g_slot[threadIdx.x * 32] = 0u;
        for (int i = threadIdx.x; i < Rn; i += 256) g_rowsum[i] = 0.0f;
    }
    const int nW    = Dh * Dh / 4;
    const int nU    = Dh * Dh / 4;
    const int nWout = Vn * Dh / 4;
    int i = blockIdx.x * 256 + threadIdx.x;
    const int stride = CVT_BLOCKS * 256;
    for (; i < nW + nU + nWout; i += stride) {
        float4 v;
        __nv_bfloat162* dst;
        if (i < nW) {
            v = ((const float4*)W)[i];
            dst = (__nv_bfloat162*)g_Wbf + 2 * (size_t)i;
        } else if (i < nW + nU) {
            int j = i - nW;
            v = ((const float4*)U)[j];
            dst = (__nv_bfloat162*)g_Ubf + 2 * (size_t)j;
        } else {
            int j = i - nW - nU;
            v = ((const float4*)Wout)[j];
            dst = (__nv_bfloat162*)g_Woutbf + 2 * (size_t)j;
        }
        dst[0] = __floats2bfloat162_rn(v.x, v.y);
        dst[1] = __floats2bfloat162_rn(v.z, v.w);
    }
}

// ---------------- embedding gather -> bf16 ----------------
__global__ __launch_bounds__(256) void embed_kernel(const int* __restrict__ idx,
                                                    const float* __restrict__ E) {
    int r = blockIdx.x;
    int id = idx[r];
    const float4* src = (const float4*)(E + (size_t)id * Dh);
    __nv_bfloat162* out = (__nv_bfloat162*)(g_xbf + (size_t)r * Dh);
    for (int i = threadIdx.x; i < Dh / 4; i += 256) {
        float4 v = src[i];
        out[2*i]   = __floats2bfloat162_rn(v.x, v.y);
        out[2*i+1] = __floats2bfloat162_rn(v.z, v.w);
    }
}

// ================= raw mma.sync bf16 NT GEMM: C[m,n] = sum_k A[m,k]*B[n,k] =================
#define BM 128
#define BN 128
#define BK 64
#define NST 3
#define AST (BM * BK * 2)
#define BST (BN * BK * 2)
#define GEMM_DSMEM (NST * (AST + BST))   // 96 KB

__device__ __forceinline__ uint32_t smem_u32(const void* p) {
    uint32_t a;
    asm("{ .reg .u64 t; cvta.to.shared.u64 t, %1; cvt.u32.u64 %0, t; }" : "=r"(a) : "l"(p));
    return a;
}
__device__ __forceinline__ void cp_async16(uint32_t dst, const void* src) {
    asm volatile("cp.async.cg.shared.global [%0], [%1], 16;" :: "r"(dst), "l"(src));
}
__device__ __forceinline__ void cp_commit() { asm volatile("cp.async.commit_group;"); }

__device__ __forceinline__ void ldsm4(uint32_t& r0, uint32_t& r1, uint32_t& r2, uint32_t& r3, uint32_t a) {
    asm volatile("ldmatrix.sync.aligned.m8n8.x4.shared.b16 {%0,%1,%2,%3}, [%4];"
                 : "=r"(r0), "=r"(r1), "=r"(r2), "=r"(r3) : "r"(a));
}
__device__ __forceinline__ void mma16816(float* d, const uint32_t* a, const uint32_t* b) {
    asm volatile("mma.sync.aligned.m16n8k16.row.col.f32.bf16.bf16.f32 "
                 "{%0,%1,%2,%3}, {%4,%5,%6,%7}, {%8,%9}, {%0,%1,%2,%3};"
                 : "+f"(d[0]), "+f"(d[1]), "+f"(d[2]), "+f"(d[3])
                 : "r"(a[0]), "r"(a[1]), "r"(a[2]), "r"(a[3]), "r"(b[0]), "r"(b[1]));
}

template <bool FUSE>
__global__ __launch_bounds__(256, 2) void gemm_mma(const __nv_bfloat16* __restrict__ A,
                                                   const __nv_bfloat16* __restrict__ Bm,
                                                   float* __restrict__ C,
                                                   int Nr, int Kr,
                                                   const float* __restrict__ bias,
                                                   float* __restrict__ rowsum) {
    extern __shared__ char smem[];
    const uint32_t sBase = smem_u32(smem);
    const uint32_t aS = sBase;
    const uint32_t bS = sBase + NST * AST;

    const int tid  = threadIdx.x;
    const int lane = tid & 31;
    const int wid  = tid >> 5;
    const int wm   = wid >> 2;
    const int wn   = wid & 3;
    const int bm = blockIdx.x, bn = blockIdx.y;
    const int KTILES = Kr / BK;

    uint32_t ld_phys[4];
    const __nv_bfloat16* aSrc[4];
    const __nv_bfloat16* bSrc[4];
    #pragma unroll
    for (int q = 0; q < 4; q++) {
        int task = q * 256 + tid;
        int row = task >> 3, ch = task & 7;
        uint32_t col = (uint32_t)ch * 16;
        ld_phys[q] = (uint32_t)row * 128 + (col ^ ((uint32_t)(row & 7) << 4));
        aSrc[q] = A  + (size_t)(bm * BM + row) * Kr + ch * 8;
        bSrc[q] = Bm + (size_t)(bn * BN + row) * Kr + ch * 8;
    }

    uint32_t aRowTerm[4], aPhase[4];
    const uint32_t aChunk = (uint32_t)(lane >> 4) * 16;
    #pragma unroll
    for (int i = 0; i < 4; i++) {
        int r = wm * 64 + i * 16 + (lane & 15);
        aRowTerm[i] = (uint32_t)r * 128;
        aPhase[i]   = (uint32_t)(r & 7) << 4;
    }
    uint32_t bRowTerm[2], bPhase[2];
    const uint32_t bChunk = (uint32_t)((lane >> 3) & 1) * 16;
    #pragma unroll
    for (int j = 0; j < 2; j++) {
        int n = wn * 32 + j * 16 + (lane & 7) + ((lane >> 4) << 3);
        bRowTerm[j] = (uint32_t)n * 128;
        bPhase[j]   = (uint32_t)(n & 7) << 4;
    }

    auto load_stage = [&](int st, int kt) {
        const int k0 = kt * BK;
        const uint32_t aOff = aS + st * AST;
        const uint32_t bOff = bS + st * BST;
        #pragma unroll
        for (int q = 0; q < 4; q++) {
            cp_async16(aOff + ld_phys[q], aSrc[q] + k0);
            cp_async16(bOff + ld_phys[q], bSrc[q] + k0);
        }
    };

    float acc[4][4][4];
    #pragma unroll
    for (int i = 0; i < 4; i++)
        #pragma unroll
        for (int j = 0; j < 4; j++)
            #pragma unroll
            for (int e = 0; e < 4; e++) acc[i][j][e] = 0.0f;

    load_stage(0, 0); cp_commit();
    load_stage(1, 1); cp_commit();

    for (int kt = 0; kt < KTILES; kt++) {
        const int st = kt % NST;
        asm volatile("cp.async.wait_group 1;" ::: "memory");
        __syncthreads();

        const int nf = kt + 2;
        if (nf < KTILES) load_stage(nf % NST, nf);
        cp_commit();

        const uint32_t aStage = aS + st * AST;
        const uint32_t bStage = bS + st * BST;
        #pragma unroll
        for (int s = 0; s < BK / 16; s++) {
            const uint32_t colA = (uint32_t)s * 32 + aChunk;
            const uint32_t colB = (uint32_t)s * 32 + bChunk;
            uint32_t a[4][4];
            #pragma unroll
            for (int i = 0; i < 4; i++)
                ldsm4(a[i][0], a[i][1], a[i][2], a[i][3],
                      aStage + aRowTerm[i] + (colA ^ aPhase[i]));
            uint32_t b[4][2];
            #pragma unroll
            for (int j = 0; j < 2; j++) {
                uint32_t r0, r1, r2, r3;
                ldsm4(r0, r1, r2, r3, bStage + bRowTerm[j] + (colB ^ bPhase[j]));
                b[2*j][0] = r0; b[2*j][1] = r1;
                b[2*j+1][0] = r2; b[2*j+1][1] = r3;
            }
            #pragma unroll
            for (int i = 0; i < 4; i++)
                #pragma unroll
                for (int j = 0; j < 4; j++)
                    mma16816(acc[i][j], a[i], b[j]);
        }
    }

    const int g = lane >> 2, tg = lane & 3;
    #pragma unroll
    for (int i = 0; i < 4; i++) {
        int row0 = bm * BM + wm * 64 + i * 16 + g;
        float p0 = 0.0f, p8 = 0.0f;
        #pragma unroll
        for (int j = 0; j < 4; j++) {
            int col = bn * BN + wn * 32 + j * 8 + tg * 2;
            float b0 = 0.0f, b1 = 0.0f;
            if (FUSE) { b0 = bias[col]; b1 = bias[col + 1]; }
            float v00 = acc[i][j][0] + b0, v01 = acc[i][j][1] + b1;
            float v10 = acc[i][j][2] + b0, v11 = acc[i][j][3] + b1;
            *(float2*)(C + (size_t)row0 * Nr + col)       = make_float2(v00, v01);
            *(float2*)(C + (size_t)(row0 + 8) * Nr + col) = make_float2(v10, v11);
            if (FUSE) {
                p0 += __expf(v00) + __expf(v01);
                p8 += __expf(v10) + __expf(v11);
            }
        }
        if (FUSE) {
            p0 += __shfl_xor_sync(0xffffffffu, p0, 1);
            p0 += __shfl_xor_sync(0xffffffffu, p0, 2);
            p8 += __shfl_xor_sync(0xffffffffu, p8, 1);
            p8 += __shfl_xor_sync(0xffffffffu, p8, 2);
            if (tg == 0) {
                atomicAdd(&rowsum[row0], p0);
                atomicAdd(&rowsum[row0 + 8], p8);
            }
        }
    }
}

// ====== persistent recurrence v11: 2 independent batch-groups x 16 blocks ======
// Group gr = bi>>4 owns batches B0 = gr*4 .. B0+3 (fully decoupled barriers).
// Block (gi = bi&15) owns 64 e's (E0 = gi*64), full K. Warp w owns k-range w*128.
// U frags bf[8][8][2] in registers. A rows: 4 real batches (bn<4), rest zero.
__global__ __launch_bounds__(256, 1) void rnn_kernel(const float* __restrict__ bWv,
                                                     const float* __restrict__ bUv) {
    const int tid  = threadIdx.x;
    const int w    = tid >> 5;
    const int lane = tid & 31;
    const int bi   = blockIdx.x;
    const int gr   = bi >> 4;          // 0..1  (batch group)
    const int gi   = bi & 15;          // 0..15
    const int B0   = gr * 4;           // first batch of group
    const int E0   = gi * 64;

    const int bn = lane >> 2;          // mma A row (batch) / B col group
    const int bk = (lane & 3) * 2;     // k pair within k16

    // B fragments: U[n = E0 + j*8 + bn][k = w*128 + s*16 + bk (+8)], j = 0..7
    uint32_t bf[8][8][2];
    #pragma unroll
    for (int j = 0; j < 8; j++)
        #pragma unroll
        for (int s = 0; s < 8; s++) {
            const __nv_bfloat16* up = g_Ubf + (size_t)(E0 + j * 8 + bn) * Dh + w * 128 + s * 16 + bk;
            bf[j][s][0] = *(const uint32_t*)up;
            bf[j][s][1] = *(const uint32_t*)(up + 8);
        }

    const int bb = tid >> 6;           // 0..3  (batch within group, reduce phase)
    const int el = tid & 63;           // 0..63 (e_local, reduce phase)
    const float bsum = bWv[E0 + el] + bUv[E0 + el];

    __shared__ float sp[8 * 256];   // per-warp partials [w][bb*64 + e_local]
    __shared__ float sh2[256];      // h floats [bb*64 + e_local]

    const bool arow = (bn < 4);     // real batch row?

    for (int t = 0; t < Tn; t++) {
        float wx = __ldcg(&g_Wx[(size_t)((B0 + bb) * Tn + t) * Dh + E0 + el]);

        float c[8][4];
        #pragma unroll
        for (int j = 0; j < 8; j++)
            #pragma unroll
            for (int q = 0; q < 4; q++) c[j][q] = 0.0f;

        if (t > 0) {
            const __nv_bfloat16* Hp = g_hcur[(t - 1) & 1];
            #pragma unroll
            for (int s = 0; s < 8; s++) {
                uint32_t aa[4];
                if (arow) {
                    const __nv_bfloat16* hp = Hp + (size_t)(B0 + bn) * Dh + w * 128 + s * 16 + bk;
                    aa[0] = __ldcg((const uint32_t*)hp);
                    aa[2] = __ldcg((const uint32_t*)(hp + 8));
                } else {
                    aa[0] = 0u; aa[2] = 0u;
                }
                aa[1] = 0u; aa[3] = 0u;
                #pragma unroll
                for (int j = 0; j < 8; j++)
                    mma16816(c[j], aa, bf[j][s]);
            }
        }

        // write warp partials: c[j][0,1] = (batch=bn(<4), e_local = j*8 + bk, +1)
        if (arow) {
            #pragma unroll
            for (int j = 0; j < 8; j++)
                *(float2*)&sp[w * 256 + bn * 64 + j * 8 + bk] = make_float2(c[j][0], c[j][1]);
        }
        __syncthreads();

        {
            float s2 = wx + bsum;
            #pragma unroll
            for (int w8 = 0; w8 < 8; w8++) s2 += sp[w8 * 256 + tid];
            sh2[tid] = tanhf(s2);
        }
        __syncthreads();

        if (tid < 128) {
            int b2 = tid >> 5, e2 = (tid & 31) * 2;   // b2 = 0..3
            __nv_bfloat162 hv = __floats2bfloat162_rn(sh2[b2 * 64 + e2], sh2[b2 * 64 + e2 + 1]);
            *(__nv_bfloat162*)&g_hcur[t & 1][(B0 + b2) * Dh + E0 + e2] = hv;
            *(__nv_bfloat162*)&g_hbf[(size_t)((B0 + b2) * Tn + t) * Dh + E0 + e2] = hv;
        }
        __syncthreads();

        // ---- per-group barrier: 16 slots, release store + 16-thread parallel poll ----
        if (tid == 0) {
            __threadfence();
            g_slot[bi * 32] = (unsigned)(t + 1);
        }
        const int base = gr * 16;
        for (;;) {
            bool ok = (tid < 16) ? (g_slot[(base + tid) * 32] >= (unsigned)(t + 1)) : true;
            if (__syncthreads_and(ok)) break;
        }
        __threadfence();
    }
}

// ---------------- final log_softmax subtract (single vectorized pass) ----------------
__global__ __launch_bounds__(256) void lse_final_kernel(float* __restrict__ C) {
    const int r = blockIdx.x;
    float4* row = (float4*)(C + (size_t)r * Vn);
    const float lse = __logf(g_rowsum[r]);
    for (int i = threadIdx.x; i < Vn / 4; i += 256) {
        float4 v = row[i];
        v.x -= lse; v.y -= lse; v.z -= lse; v.w -= lse;
        row[i] = v;
    }
}

// ---------------- launch ----------------
extern "C" void kernel_launch(void* const* d_in, const int* in_sizes, int n_in,
                              void* d_out, int out_size) {
    const int*   idx  = (const int*)d_in[0];
    const float* E    = (const float*)d_in[1];
    const float* W    = (const float*)d_in[2];
    const float* bW   = (const float*)d_in[3];
    const float* U    = (const float*)d_in[4];
    const float* bU   = (const float*)d_in[5];
    const float* Wout = (const float*)d_in[6];
    const float* bout = (const float*)d_in[7];
    float* out = (float*)d_out;

    void *p_xbf, *p_Wbf, *p_Woutbf, *p_Wx, *p_hbf, *p_rowsum;
    cudaGetSymbolAddress(&p_xbf,    g_xbf);
    cudaGetSymbolAddress(&p_Wbf,    g_Wbf);
    cudaGetSymbolAddress(&p_Woutbf, g_Woutbf);
    cudaGetSymbolAddress(&p_Wx,     g_Wx);
    cudaGetSymbolAddress(&p_hbf,    g_hbf);
    cudaGetSymbolAddress(&p_rowsum, g_rowsum);

    static int attr_set = 0;
    if (!attr_set) {
        cudaFuncSetAttribute(gemm_mma<false>, cudaFuncAttributeMaxDynamicSharedMemorySize, GEMM_DSMEM);
        cudaFuncSetAttribute(gemm_mma<true>,  cudaFuncAttributeMaxDynamicSharedMemorySize, GEMM_DSMEM);
        attr_set = 1;
    }

    // 1) cvt W/U/Wout + zero slots/rowsum
    cvt_kernel<<<CVT_BLOCKS, 256>>>(W, U, Wout);

    // 2) embedding gather
    embed_kernel<<<Rn, 256>>>(idx, E);

    // 3) input projection: Wx[r,e] = sum_d x[r,d] * W[e,d]
    gemm_mma<false><<<dim3(Rn / BM, Dh / BN), 256, GEMM_DSMEM>>>(
        (const __nv_bfloat16*)p_xbf, (const __nv_bfloat16*)p_Wbf, (float*)p_Wx,
        Dh, Dh, nullptr, nullptr);

    // 4) recurrence (tensor-core, 2 groups x 16 blocks)
    rnn_kernel<<<RB, 256>>>(bW, bU);

    // 5) output projection with fused bias + exp-sum epilogue
    gemm_mma<true><<<dim3(Rn / BM, Vn / BN), 256, GEMM_DSMEM>>>(
        (const __nv_bfloat16*)p_hbf, (const __nv_bfloat16*)p_Woutbf, out,
        Vn, Dh, bout, (float*)p_rowsum);

    // 6) final: subtract log(sum exp) per row
    lse_final_kernel<<<Rn, 256>>>(out);
}